// round 11
// baseline (speedup 1.0000x reference)
#include <cuda_runtime.h>
#include <math.h>

// Problem constants (match reference)
#define BATCH   16384
#define CTX     8
#define NEGS    5
#define NROWS   (CTX + 1 + NEGS)   // 14 gathered rows per batch
#define DIM     128
#define ROWF4   (DIM / 4)          // 32 float4 per embedding row
#define WPB     8                  // warps per block
#define TPB     (WPB * 32)
#define NBLOCKS 592                // 148 SMs x 4 CTAs: exactly one balanced wave
#define TOTAL_WARPS (NBLOCKS * WPB) // 4736

// SoA partials: g_part[k][block], k in {0..5}: [0]=s_pos, [1..5]=s_neg[n]
__device__ float g_part[6][NBLOCKS];
__device__ unsigned int g_ticket;   // zero-init; finalizing block resets it

__device__ __forceinline__ float log_sigmoid(float x) {
    return (x >= 0.0f) ? -log1pf(expf(-x)) : (x - log1pf(expf(x)));
}

__global__ __launch_bounds__(TPB, 4) void cbow_fused_kernel(
    const int* __restrict__ pos_u,   // [B, C]
    const int* __restrict__ pos_w,   // [B]
    const int* __restrict__ neg_w,   // [B, N]
    const float4* __restrict__ Wv,   // [VOCAB, 32] as float4
    float* __restrict__ out)
{
    const int lane = threadIdx.x & 31;
    const int wid  = threadIdx.x >> 5;
    const int gw   = blockIdx.x * WPB + wid;   // global warp id

    // Per-thread loss partials accumulated across this warp's batches.
    float acc[6];
#pragma unroll
    for (int k = 0; k < 6; k++) acc[k] = 0.0f;

    // Grid-stride over batches: every SM holds exactly 4 CTAs, so per-SM
    // work is ~uniform (vs 512-block config where 68 SMs carried 33% more).
    for (int b = gw; b < BATCH; b += TOTAL_WARPS) {
        // Lanes 0..7: context idx; lane 8: positive; lanes 9..13: negatives.
        int idx = 0;
        if (lane < CTX)                 idx = pos_u[b * CTX + lane];
        else if (lane == CTX)           idx = pos_w[b];
        else if (lane < NROWS)          idx = neg_w[b * NEGS + (lane - CTX - 1)];

        // Issue ALL 14 row loads up front (maximum MLP). .cg: no L1 alloc
        // (cross-SM touch pattern -> ~0 L1 reuse; measured R2 vs R5).
        float4 r[NROWS];
#pragma unroll
        for (int t = 0; t < NROWS; t++) {
            int row = __shfl_sync(0xffffffffu, idx, t);
            r[t] = __ldcg(&Wv[(size_t)row * ROWF4 + lane]);
        }

        // Context sum (rows 0..7).
        float4 us = r[0];
#pragma unroll
        for (int c = 1; c < CTX; c++) {
            us.x += r[c].x; us.y += r[c].y; us.z += r[c].z; us.w += r[c].w;
        }

        // 6 dots: target rows 8..13 against Usum; accumulate across batches.
#pragma unroll
        for (int t = 0; t < 6; t++) {
            const float4 v = r[CTX + t];
            acc[t] += us.x * v.x + us.y * v.y + us.z * v.z + us.w * v.w;
        }
    }

    // Warp reduction of the 6 accumulated partials.
#pragma unroll
    for (int t = 0; t < 6; t++) {
        float v = acc[t];
#pragma unroll
        for (int o = 16; o > 0; o >>= 1)
            v += __shfl_xor_sync(0xffffffffu, v, o);
        acc[t] = v;
    }

    __shared__ float smem[6][WPB];
    __shared__ bool  s_last;
    if (lane == 0) {
#pragma unroll
        for (int t = 0; t < 6; t++) smem[t][wid] = acc[t];
    }
    __syncthreads();

    // Thread 0 publishes all 6 block partials (st.cg -> L2), then
    // release-orders them with an acq_rel ticket atomic. No __threadfence():
    // gpu-scope fence emits CCTL.IVALL (L1 wipe — the R3 regression).
    if (threadIdx.x == 0) {
        unsigned int mine;
#pragma unroll
        for (int k = 0; k < 6; k++) {
            float s = 0.0f;
#pragma unroll
            for (int i = 0; i < WPB; i++) s += smem[k][i];
            __stcg(&g_part[k][blockIdx.x], s);
        }
        asm volatile("atom.acq_rel.gpu.global.add.u32 %0, [%1], %2;"
                     : "=r"(mine) : "l"(&g_ticket), "r"(1u) : "memory");
        s_last = (mine == NBLOCKS - 1);
    }
    __syncthreads();

    if (s_last) {
        // Reduce 6 x 592 L2-resident partials (ldcg: L2-direct reads).
        const int t = threadIdx.x;
        float s[6];
#pragma unroll
        for (int k = 0; k < 6; k++) s[k] = 0.0f;
        for (int i = t; i < NBLOCKS; i += TPB) {
#pragma unroll
            for (int k = 0; k < 6; k++) s[k] += __ldcg(&g_part[k][i]);
        }
#pragma unroll
        for (int k = 0; k < 6; k++) {
#pragma unroll
            for (int o = 16; o > 0; o >>= 1)
                s[k] += __shfl_xor_sync(0xffffffffu, s[k], o);
        }
        __shared__ float fin[6][WPB];
        if (lane == 0) {
#pragma unroll
            for (int k = 0; k < 6; k++) fin[k][wid] = s[k];
        }
        __syncthreads();
        if (t == 0) {
            float tot[6];
#pragma unroll
            for (int k = 0; k < 6; k++) {
                float a = 0.0f;
#pragma unroll
                for (int i = 0; i < WPB; i++) a += fin[k][i];
                tot[k] = a;
            }
            float loss = -log_sigmoid(tot[0]);            // loss1
#pragma unroll
            for (int n = 0; n < NEGS; n++)
                loss -= log_sigmoid(-tot[1 + n]);         // - loss2
            out[0] = loss;
            g_ticket = 0;                                  // reset for next replay
        }
    }
}

extern "C" void kernel_launch(void* const* d_in, const int* in_sizes, int n_in,
                              void* d_out, int out_size) {
    const int*    pos_u = (const int*)d_in[0];
    const int*    pos_w = (const int*)d_in[1];
    const int*    neg_w = (const int*)d_in[2];
    const float4* Wv    = (const float4*)d_in[3];
    float*        out   = (float*)d_out;

    (void)in_sizes; (void)n_in; (void)out_size;

    cbow_fused_kernel<<<NBLOCKS, TPB>>>(pos_u, pos_w, neg_w, Wv, out);
}

// round 13
// speedup vs baseline: 1.1248x; 1.1248x over previous
#include <cuda_runtime.h>
#include <math.h>

// Problem constants (match reference)
#define BATCH   16384
#define CTX     8
#define NEGS    5
#define NROWS   (CTX + 1 + NEGS)   // 14 gathered rows per batch
#define DIM     128
#define ROWF4   (DIM / 4)          // 32 float4 per embedding row
#define WPB     8                  // warps per block
#define TPB     (WPB * 32)
#define NBLOCKS 592                // 148 SMs x 4 CTAs: one balanced wave
#define ITERS   4                  // static unroll; tail slots predicated off

// SoA partials: g_part[k][block], k in {0..5}: [0]=s_pos, [1..5]=s_neg[n]
__device__ float g_part[6][NBLOCKS];
__device__ unsigned int g_ticket;   // zero-init; finalizing block resets it

__device__ __forceinline__ float log_sigmoid(float x) {
    return (x >= 0.0f) ? -log1pf(expf(-x)) : (x - log1pf(expf(x)));
}

__global__ __launch_bounds__(TPB, 4) void cbow_fused_kernel(
    const int* __restrict__ pos_u,   // [B, C]
    const int* __restrict__ pos_w,   // [B]
    const int* __restrict__ neg_w,   // [B, N]
    const float4* __restrict__ Wv,   // [VOCAB, 32] as float4
    float* __restrict__ out)
{
    const int lane = threadIdx.x & 31;
    const int wid  = threadIdx.x >> 5;

    // Per-thread loss partials accumulated across ITERS batch slots.
    float acc[6];
#pragma unroll
    for (int k = 0; k < 6; k++) acc[k] = 0.0f;

#pragma unroll
    for (int it = 0; it < ITERS; it++) {
        const int b = (it * NBLOCKS + blockIdx.x) * WPB + wid;  // batch slot
        const bool valid = (b < BATCH);

        // Lanes 0..7: context idx; lane 8: positive; lanes 9..13: negatives.
        int idx = 0;
        if (valid) {
            if (lane < CTX)                 idx = pos_u[b * CTX + lane];
            else if (lane == CTX)           idx = pos_w[b];
            else if (lane < NROWS)          idx = neg_w[b * NEGS + (lane - CTX - 1)];
        }

        // All 14 row loads issued up front (max MLP); invalid slots load
        // zeros via predication — zero rows contribute zero to the dots.
        float4 r[NROWS];
#pragma unroll
        for (int t = 0; t < NROWS; t++) {
            int row = __shfl_sync(0xffffffffu, idx, t);
            r[t] = valid ? __ldcg(&Wv[(size_t)row * ROWF4 + lane])
                         : make_float4(0.f, 0.f, 0.f, 0.f);
        }

        // Context sum (rows 0..7).
        float4 us = r[0];
#pragma unroll
        for (int c = 1; c < CTX; c++) {
            us.x += r[c].x; us.y += r[c].y; us.z += r[c].z; us.w += r[c].w;
        }

        // 6 dots: target rows 8..13 against Usum; accumulate across slots.
#pragma unroll
        for (int t = 0; t < 6; t++) {
            const float4 v = r[CTX + t];
            acc[t] += us.x * v.x + us.y * v.y + us.z * v.z + us.w * v.w;
        }
    }

    // Warp reduction of the 6 accumulated partials.
#pragma unroll
    for (int t = 0; t < 6; t++) {
        float v = acc[t];
#pragma unroll
        for (int o = 16; o > 0; o >>= 1)
            v += __shfl_xor_sync(0xffffffffu, v, o);
        acc[t] = v;
    }

    __shared__ float smem[6][WPB];
    __shared__ bool  s_last;
    if (lane == 0) {
#pragma unroll
        for (int t = 0; t < 6; t++) smem[t][wid] = acc[t];
    }
    __syncthreads();

    // Thread 0 publishes all 6 block partials (st.cg -> L2), then
    // release-orders them with an acq_rel ticket atomic. No __threadfence():
    // gpu-scope fence emits CCTL.IVALL (L1 wipe — the R3 regression).
    if (threadIdx.x == 0) {
        unsigned int mine;
#pragma unroll
        for (int k = 0; k < 6; k++) {
            float s = 0.0f;
#pragma unroll
            for (int i = 0; i < WPB; i++) s += smem[k][i];
            __stcg(&g_part[k][blockIdx.x], s);
        }
        asm volatile("atom.acq_rel.gpu.global.add.u32 %0, [%1], %2;"
                     : "=r"(mine) : "l"(&g_ticket), "r"(1u) : "memory");
        s_last = (mine == NBLOCKS - 1);
    }
    __syncthreads();

    if (s_last) {
        // Reduce 6 x 592 L2-resident partials (ldcg: L2-direct reads).
        const int t = threadIdx.x;
        float s[6];
#pragma unroll
        for (int k = 0; k < 6; k++) s[k] = 0.0f;
        for (int i = t; i < NBLOCKS; i += TPB) {
#pragma unroll
            for (int k = 0; k < 6; k++) s[k] += __ldcg(&g_part[k][i]);
        }
#pragma unroll
        for (int k = 0; k < 6; k++) {
#pragma unroll
            for (int o = 16; o > 0; o >>= 1)
                s[k] += __shfl_xor_sync(0xffffffffu, s[k], o);
        }
        __shared__ float fin[6][WPB];
        if (lane == 0) {
#pragma unroll
            for (int k = 0; k < 6; k++) fin[k][wid] = s[k];
        }
        __syncthreads();
        if (t == 0) {
            float tot[6];
#pragma unroll
            for (int k = 0; k < 6; k++) {
                float a = 0.0f;
#pragma unroll
                for (int i = 0; i < WPB; i++) a += fin[k][i];
                tot[k] = a;
            }
            float loss = -log_sigmoid(tot[0]);            // loss1
#pragma unroll
            for (int n = 0; n < NEGS; n++)
                loss -= log_sigmoid(-tot[1 + n]);         // - loss2
            out[0] = loss;
            g_ticket = 0;                                  // reset for next replay
        }
    }
}

extern "C" void kernel_launch(void* const* d_in, const int* in_sizes, int n_in,
                              void* d_out, int out_size) {
    const int*    pos_u = (const int*)d_in[0];
    const int*    pos_w = (const int*)d_in[1];
    const int*    neg_w = (const int*)d_in[2];
    const float4* Wv    = (const float4*)d_in[3];
    float*        out   = (float*)d_out;

    (void)in_sizes; (void)n_in; (void)out_size;

    cbow_fused_kernel<<<NBLOCKS, TPB>>>(pos_u, pos_w, neg_w, Wv, out);
}